// round 10
// baseline (speedup 1.0000x reference)
#include <cuda_runtime.h>
#include <cuda_bf16.h>

#define N_NODES   50000
#define N_EDGES   800000
#define DIM       128
#define NUM_GRAPHS 64
#define NUM_CLASSES 3
#define TOT_ENTRIES (N_EDGES + N_NODES)
#define NSEG ((N_NODES + 127) / 128)       // 391

// ---------------- scratch (device globals; sanctioned, no allocation) ----------------
__device__ int   v9_is64;                  // 1 if index inputs are int64, 0 if int32
__device__ int   v9_deg[N_NODES];
__device__ float v9_dinv[N_NODES];
__device__ int   v9_segsum[NSEG];
__device__ int   v9_segoff[NSEG];
__device__ int   v9_rowptr[N_NODES + 1];
__device__ int   v9_cursor[N_NODES];
__device__ int   v9_csrc[TOT_ENTRIES];
__device__ float v9_T [N_NODES * DIM];
__device__ float v9_hA[N_NODES * DIM];
__device__ float v9_hB[N_NODES * DIM];
__device__ float v9_pooled[NUM_GRAPHS * DIM];
__device__ int   v9_cnt[NUM_GRAPHS];
__device__ float v9_hid[NUM_GRAPHS * DIM];

// dtype-adaptive index load: element i of a logical index array.
// int64 layout: little-endian low word at 2*i. int32 layout: word at i.
__device__ __forceinline__ int ld_idx(const int* p, int i) {
    return v9_is64 ? p[2 * i] : p[i];
}

__device__ __forceinline__ int v9_incl_scan(int v, int lane) {
#pragma unroll
    for (int o = 1; o < 32; o <<= 1) {
        int n = __shfl_up_sync(0xffffffffu, v, o);
        if (lane >= o) v += n;
    }
    return v;
}

// ---------------- dtype detection (single warp) ----------------
// Probe odd 32-bit words of edge_index within the first N_EDGES logical elements:
// safe under BOTH interpretations (indices < 2*N_EDGES words, the int32-layout
// buffer size). If int64: these are high words of nonneg values < 2^31 -> all 0.
// If int32: these are random node ids -> some nonzero.
__global__ void v9_detect(const int* ei32) {
    int lane = threadIdx.x;
    int acc = 0;
    for (int i = lane; i < 4096; i += 32) acc |= ei32[2 * i + 1];
#pragma unroll
    for (int o = 16; o > 0; o >>= 1) acc |= __shfl_down_sync(0xffffffffu, acc, o);
    if (lane == 0) v9_is64 = (acc == 0) ? 1 : 0;
}

// ---------------- preprocessing ----------------
__global__ void v9_init() {
    int i = blockIdx.x * blockDim.x + threadIdx.x;
    if (i < N_NODES) v9_deg[i] = 1;               // self-loop pre-counted
    if (i < NUM_GRAPHS * DIM) v9_pooled[i] = 0.f;
    if (i < NUM_GRAPHS) v9_cnt[i] = 0;
}

__global__ void v9_count(const int* ei32, const int* batch32) {
    int i = blockIdx.x * blockDim.x + threadIdx.x;
    if (i < N_EDGES) {
        int dst = ld_idx(ei32, N_EDGES + i);
        atomicAdd(&v9_deg[dst], 1);
    }
    if (i < N_NODES) {
        int g = ld_idx(batch32, i);
        atomicAdd(&v9_cnt[g], 1);
    }
}

__global__ void v9_rsqrt() {
    int i = blockIdx.x * blockDim.x + threadIdx.x;
    if (i < N_NODES) v9_dinv[i] = rsqrtf((float)v9_deg[i]);
}

// stage 1: per-segment (128 nodes) degree sums, one warp per segment
__global__ void v9_segsum_k() {
    int w    = (blockIdx.x * blockDim.x + threadIdx.x) >> 5;
    int lane = threadIdx.x & 31;
    if (w >= NSEG) return;
    int s = 0;
#pragma unroll
    for (int c = 0; c < 4; c++) {
        int i = w * 128 + c * 32 + lane;
        if (i < N_NODES) s += v9_deg[i];
    }
#pragma unroll
    for (int o = 16; o > 0; o >>= 1) s += __shfl_down_sync(0xffffffffu, s, o);
    if (lane == 0) v9_segsum[w] = s;
}

// stage 2: exclusive scan over NSEG segment sums, single warp
__global__ void v9_segscan_k() {
    int lane = threadIdx.x;
    int carry = 0;
    for (int base = 0; base < NSEG; base += 32) {
        int i = base + lane;
        int v = (i < NSEG) ? v9_segsum[i] : 0;
        int s = v9_incl_scan(v, lane);
        if (i < NSEG) v9_segoff[i] = carry + s - v;
        carry += __shfl_sync(0xffffffffu, s, 31);
    }
}

// stage 3: per-segment node-level exclusive scan -> rowptr + cursor
__global__ void v9_rowptr_k() {
    int w    = (blockIdx.x * blockDim.x + threadIdx.x) >> 5;
    int lane = threadIdx.x & 31;
    if (w >= NSEG) return;
    int carry = v9_segoff[w];
#pragma unroll
    for (int c = 0; c < 4; c++) {
        int i = w * 128 + c * 32 + lane;
        int v = (i < N_NODES) ? v9_deg[i] : 0;
        int s = v9_incl_scan(v, lane);
        if (i < N_NODES) {
            int ex = carry + s - v;
            v9_rowptr[i] = ex;
            v9_cursor[i] = ex;
        }
        carry += __shfl_sync(0xffffffffu, s, 31);
    }
    if (w == NSEG - 1 && lane == 0) v9_rowptr[N_NODES] = carry;
}

// scatter edges + self-loops into CSR-by-destination
__global__ void v9_fill(const int* ei32) {
    int i = blockIdx.x * blockDim.x + threadIdx.x;
    if (i < N_EDGES) {
        int src = ld_idx(ei32, i);
        int dst = ld_idx(ei32, N_EDGES + i);
        int pos = atomicAdd(&v9_cursor[dst], 1);
        v9_csrc[pos] = src;
    } else if (i < TOT_ENTRIES) {
        int n = i - N_EDGES;
        int pos = atomicAdd(&v9_cursor[n], 1);
        v9_csrc[pos] = n;
    }
}

// ---------------- GEMM (shared-free, register-blocked): v9_T = src @ W ----------------
// One warp handles 4 rows. Lane owns columns {lane, lane+32, lane+64, lane+96}.
// SRC: 0 -> Xext, 1 -> v9_hA, 2 -> v9_hB
template<int SRC>
__global__ __launch_bounds__(256) void v9_gemm(const float* Xext, const float* W) {
    int w    = (blockIdx.x * blockDim.x + threadIdx.x) >> 5;
    int lane = threadIdx.x & 31;
    int r0   = w * 4;
    if (r0 >= N_NODES) return;

    // stage X rows into registers: xr[row][q] holds X[row][q*32+lane]
    float xr[4][4];
#pragma unroll
    for (int j = 0; j < 4; j++) {
        int row = r0 + j;
#pragma unroll
        for (int q = 0; q < 4; q++) {
            float v = 0.f;
            if (row < N_NODES) {
                int k = q * 32 + lane;
                if (SRC == 0)      v = Xext[row * 128 + k];
                else if (SRC == 1) v = v9_hA[row * 128 + k];
                else               v = v9_hB[row * 128 + k];
            }
            xr[j][q] = v;
        }
    }

    float acc[4][4];
#pragma unroll
    for (int j = 0; j < 4; j++)
#pragma unroll
        for (int q = 0; q < 4; q++) acc[j][q] = 0.f;

#pragma unroll
    for (int q = 0; q < 4; q++) {
#pragma unroll 8
        for (int s = 0; s < 32; s++) {
            int k = q * 32 + s;
            float w0 = W[k * 128 + lane];
            float w1 = W[k * 128 + 32 + lane];
            float w2 = W[k * 128 + 64 + lane];
            float w3 = W[k * 128 + 96 + lane];
#pragma unroll
            for (int j = 0; j < 4; j++) {
                float xv = __shfl_sync(0xffffffffu, xr[j][q], s);
                acc[j][0] = fmaf(xv, w0, acc[j][0]);
                acc[j][1] = fmaf(xv, w1, acc[j][1]);
                acc[j][2] = fmaf(xv, w2, acc[j][2]);
                acc[j][3] = fmaf(xv, w3, acc[j][3]);
            }
        }
    }

#pragma unroll
    for (int j = 0; j < 4; j++) {
        int row = r0 + j;
        if (row < N_NODES) {
#pragma unroll
            for (int q = 0; q < 4; q++)
                v9_T[row * 128 + q * 32 + lane] = acc[j][q];
        }
    }
}

// ---------------- aggregation: one warp per node, lane owns 4 strided cols ----------------
// out[n] = relu?( dinv[n] * sum_s dinv[s]*v9_T[s] + b )
template<int DST, int RELU>
__global__ __launch_bounds__(256) void v9_agg(const float* bias) {
    int node = (blockIdx.x * blockDim.x + threadIdx.x) >> 5;
    int lane = threadIdx.x & 31;
    if (node >= N_NODES) return;

    int beg = v9_rowptr[node];
    int end = v9_rowptr[node + 1];

    float a0 = 0.f, a1 = 0.f, a2 = 0.f, a3 = 0.f;
    int e = beg;
    for (; e + 1 < end; e += 2) {
        int s0 = v9_csrc[e];
        int s1 = v9_csrc[e + 1];
        float w0 = v9_dinv[s0];
        float w1 = v9_dinv[s1];
        const float* p0 = &v9_T[s0 * 128 + lane];
        const float* p1 = &v9_T[s1 * 128 + lane];
        float u0 = p0[0], u1 = p0[32], u2 = p0[64], u3 = p0[96];
        float q0 = p1[0], q1 = p1[32], q2 = p1[64], q3 = p1[96];
        a0 = fmaf(w0, u0, a0); a1 = fmaf(w0, u1, a1);
        a2 = fmaf(w0, u2, a2); a3 = fmaf(w0, u3, a3);
        a0 = fmaf(w1, q0, a0); a1 = fmaf(w1, q1, a1);
        a2 = fmaf(w1, q2, a2); a3 = fmaf(w1, q3, a3);
    }
    if (e < end) {
        int s = v9_csrc[e];
        float w = v9_dinv[s];
        const float* p = &v9_T[s * 128 + lane];
        a0 = fmaf(w, p[0],  a0); a1 = fmaf(w, p[32], a1);
        a2 = fmaf(w, p[64], a2); a3 = fmaf(w, p[96], a3);
    }
    float dn = v9_dinv[node];
    float o0 = fmaf(a0, dn, bias[lane]);
    float o1 = fmaf(a1, dn, bias[lane + 32]);
    float o2 = fmaf(a2, dn, bias[lane + 64]);
    float o3 = fmaf(a3, dn, bias[lane + 96]);
    if (RELU) {
        o0 = fmaxf(o0, 0.f); o1 = fmaxf(o1, 0.f);
        o2 = fmaxf(o2, 0.f); o3 = fmaxf(o3, 0.f);
    }
    float* Out = (DST == 1) ? v9_hA : v9_hB;
    Out[node * 128 + lane]      = o0;
    Out[node * 128 + lane + 32] = o1;
    Out[node * 128 + lane + 64] = o2;
    Out[node * 128 + lane + 96] = o3;
}

// ---------------- pooling (batch sorted; reads v9_hA) ----------------
#define POOL_CHUNK 256
__global__ void v9_pool(const int* batch32) {
    int f  = threadIdx.x;                      // 128 threads = feature
    int n0 = blockIdx.x * POOL_CHUNK;
    int n1 = n0 + POOL_CHUNK;
    if (n1 > N_NODES) n1 = N_NODES;
    if (n0 >= N_NODES) return;

    int cur = ld_idx(batch32, n0);
    float local = 0.f;
    for (int n = n0; n < n1; n++) {
        int g = ld_idx(batch32, n);
        if (g != cur) {
            atomicAdd(&v9_pooled[cur * DIM + f], local);
            local = 0.f;
            cur = g;
        }
        local += v9_hA[n * DIM + f];
    }
    atomicAdd(&v9_pooled[cur * DIM + f], local);
}

// ---------------- classifier MLP ----------------
__global__ void v9_mlp1(const float* C1, const float* bc1) {
    int idx = blockIdx.x * blockDim.x + threadIdx.x;
    if (idx >= NUM_GRAPHS * DIM) return;
    int g = idx >> 7, c = idx & 127;
    float invc = 1.f / fmaxf((float)v9_cnt[g], 1.f);
    float s = bc1[c];
#pragma unroll 8
    for (int k = 0; k < 128; k++)
        s = fmaf(v9_pooled[g * 128 + k] * invc, C1[k * 128 + c], s);
    v9_hid[idx] = fmaxf(s, 0.f);
}

__global__ void v9_mlp2(const float* C2, const float* bc2, float* out) {
    int idx = threadIdx.x;
    if (idx >= NUM_GRAPHS * NUM_CLASSES) return;
    int g = idx / NUM_CLASSES, c = idx % NUM_CLASSES;
    float s = bc2[c];
#pragma unroll 8
    for (int k = 0; k < 128; k++)
        s = fmaf(v9_hid[g * 128 + k], C2[k * NUM_CLASSES + c], s);
    out[idx] = s;
}

// ---------------- launch ----------------
extern "C" void kernel_launch(void* const* d_in, const int* in_sizes, int n_in,
                              void* d_out, int out_size) {
    const float* x       = (const float*)d_in[0];
    const int*   ei32    = (const int*)d_in[1];     // width detected at runtime
    const int*   batch32 = (const int*)d_in[2];
    const float* W1 = (const float*)d_in[3];  const float* b1 = (const float*)d_in[4];
    const float* W2 = (const float*)d_in[5];  const float* b2 = (const float*)d_in[6];
    const float* W3 = (const float*)d_in[7];  const float* b3 = (const float*)d_in[8];
    const float* C1 = (const float*)d_in[9];  const float* bc1 = (const float*)d_in[10];
    const float* C2 = (const float*)d_in[11]; const float* bc2 = (const float*)d_in[12];
    float* out = (float*)d_out;

    const int TPB = 256;
    const int SEG_BLOCKS = (NSEG * 32 + TPB - 1) / TPB;

    v9_detect <<<1, 32>>>(ei32);
    v9_init   <<<(N_NODES + TPB - 1) / TPB, TPB>>>();
    v9_count  <<<(N_EDGES + TPB - 1) / TPB, TPB>>>(ei32, batch32);
    v9_rsqrt  <<<(N_NODES + TPB - 1) / TPB, TPB>>>();
    v9_segsum_k <<<SEG_BLOCKS, TPB>>>();
    v9_segscan_k<<<1, 32>>>();
    v9_rowptr_k <<<SEG_BLOCKS, TPB>>>();
    v9_fill   <<<(TOT_ENTRIES + TPB - 1) / TPB, TPB>>>(ei32);

    const int GEMM_BLOCKS = ((N_NODES + 3) / 4 * 32 + TPB - 1) / TPB;
    const int AGG_BLOCKS  = (N_NODES * 32 + TPB - 1) / TPB;

    v9_gemm<0><<<GEMM_BLOCKS, TPB>>>(x, W1);
    v9_agg<1, 1><<<AGG_BLOCKS, TPB>>>(b1);
    v9_gemm<1><<<GEMM_BLOCKS, TPB>>>(x, W2);
    v9_agg<2, 1><<<AGG_BLOCKS, TPB>>>(b2);
    v9_gemm<2><<<GEMM_BLOCKS, TPB>>>(x, W3);
    v9_agg<1, 0><<<AGG_BLOCKS, TPB>>>(b3);

    v9_pool<<<(N_NODES + POOL_CHUNK - 1) / POOL_CHUNK, 128>>>(batch32);
    v9_mlp1<<<(NUM_GRAPHS * DIM + TPB - 1) / TPB, TPB>>>(C1, bc1);
    v9_mlp2<<<1, 256>>>(C2, bc2, out);
}

// round 11
// speedup vs baseline: 1.0034x; 1.0034x over previous
#include <cuda_runtime.h>
#include <cuda_bf16.h>

#define N_NODES   50000
#define N_EDGES   800000
#define DIM       128
#define NUM_GRAPHS 64
#define NUM_CLASSES 3
#define TOT_ENTRIES (N_EDGES + N_NODES)
#define NSEG ((N_NODES + 127) / 128)       // 391

// ---------------- scratch (device globals; sanctioned, no allocation) ----------------
__device__ int   v9_is64;                  // 1 if index inputs are int64, 0 if int32
__device__ int   v9_deg[N_NODES];
__device__ float v9_dinv[N_NODES];
__device__ int   v9_segsum[NSEG];
__device__ int   v9_segoff[NSEG];
__device__ int   v9_rowptr[N_NODES + 1];
__device__ int   v9_cursor[N_NODES];
__device__ __align__(8)  int2  v9_edge[TOT_ENTRIES];   // (src, dinv[src] bits)
__device__ __align__(16) float v9_T [N_NODES * DIM];
__device__ __align__(16) float v9_hA[N_NODES * DIM];
__device__ __align__(16) float v9_hB[N_NODES * DIM];
__device__ __align__(16) float v9_pooled[NUM_GRAPHS * DIM];
__device__ int   v9_cnt[NUM_GRAPHS];
__device__ __align__(16) float v9_hid[NUM_GRAPHS * DIM];

// dtype-adaptive index load: element i of a logical index array.
__device__ __forceinline__ int ld_idx(const int* p, int i) {
    return v9_is64 ? p[2 * i] : p[i];
}

__device__ __forceinline__ int v9_incl_scan(int v, int lane) {
#pragma unroll
    for (int o = 1; o < 32; o <<= 1) {
        int n = __shfl_up_sync(0xffffffffu, v, o);
        if (lane >= o) v += n;
    }
    return v;
}

// ---------------- dtype detection (single warp) ----------------
__global__ void v9_detect(const int* ei32) {
    int lane = threadIdx.x;
    int acc = 0;
    for (int i = lane; i < 4096; i += 32) acc |= ei32[2 * i + 1];
#pragma unroll
    for (int o = 16; o > 0; o >>= 1) acc |= __shfl_down_sync(0xffffffffu, acc, o);
    if (lane == 0) v9_is64 = (acc == 0) ? 1 : 0;
}

// ---------------- preprocessing ----------------
__global__ void v9_init() {
    int i = blockIdx.x * blockDim.x + threadIdx.x;
    if (i < N_NODES) v9_deg[i] = 1;               // self-loop pre-counted
    if (i < NUM_GRAPHS * DIM) v9_pooled[i] = 0.f;
    if (i < NUM_GRAPHS) v9_cnt[i] = 0;
}

__global__ void v9_count(const int* ei32, const int* batch32) {
    int i = blockIdx.x * blockDim.x + threadIdx.x;
    if (i < N_EDGES) {
        int dst = ld_idx(ei32, N_EDGES + i);
        atomicAdd(&v9_deg[dst], 1);
    }
    if (i < N_NODES) {
        int g = ld_idx(batch32, i);
        atomicAdd(&v9_cnt[g], 1);
    }
}

__global__ void v9_rsqrt() {
    int i = blockIdx.x * blockDim.x + threadIdx.x;
    if (i < N_NODES) v9_dinv[i] = rsqrtf((float)v9_deg[i]);
}

__global__ void v9_segsum_k() {
    int w    = (blockIdx.x * blockDim.x + threadIdx.x) >> 5;
    int lane = threadIdx.x & 31;
    if (w >= NSEG) return;
    int s = 0;
#pragma unroll
    for (int c = 0; c < 4; c++) {
        int i = w * 128 + c * 32 + lane;
        if (i < N_NODES) s += v9_deg[i];
    }
#pragma unroll
    for (int o = 16; o > 0; o >>= 1) s += __shfl_down_sync(0xffffffffu, s, o);
    if (lane == 0) v9_segsum[w] = s;
}

__global__ void v9_segscan_k() {
    int lane = threadIdx.x;
    int carry = 0;
    for (int base = 0; base < NSEG; base += 32) {
        int i = base + lane;
        int v = (i < NSEG) ? v9_segsum[i] : 0;
        int s = v9_incl_scan(v, lane);
        if (i < NSEG) v9_segoff[i] = carry + s - v;
        carry += __shfl_sync(0xffffffffu, s, 31);
    }
}

__global__ void v9_rowptr_k() {
    int w    = (blockIdx.x * blockDim.x + threadIdx.x) >> 5;
    int lane = threadIdx.x & 31;
    if (w >= NSEG) return;
    int carry = v9_segoff[w];
#pragma unroll
    for (int c = 0; c < 4; c++) {
        int i = w * 128 + c * 32 + lane;
        int v = (i < N_NODES) ? v9_deg[i] : 0;
        int s = v9_incl_scan(v, lane);
        if (i < N_NODES) {
            int ex = carry + s - v;
            v9_rowptr[i] = ex;
            v9_cursor[i] = ex;
        }
        carry += __shfl_sync(0xffffffffu, s, 31);
    }
    if (w == NSEG - 1 && lane == 0) v9_rowptr[N_NODES] = carry;
}

// scatter edges + self-loops; record (src, dinv[src]) per entry
__global__ void v9_fill(const int* ei32) {
    int i = blockIdx.x * blockDim.x + threadIdx.x;
    if (i < N_EDGES) {
        int src = ld_idx(ei32, i);
        int dst = ld_idx(ei32, N_EDGES + i);
        int pos = atomicAdd(&v9_cursor[dst], 1);
        v9_edge[pos] = make_int2(src, __float_as_int(v9_dinv[src]));
    } else if (i < TOT_ENTRIES) {
        int n = i - N_EDGES;
        int pos = atomicAdd(&v9_cursor[n], 1);
        v9_edge[pos] = make_int2(n, __float_as_int(v9_dinv[n]));
    }
}

// ---------------- GEMM: v9_T[N,128] = src[N,128] @ W[128,128] ----------------
// smem-tiled, float4. BM=64 rows/block, 256 threads, 4x8 outputs each.
// SRC: 0 -> Xext, 1 -> v9_hA, 2 -> v9_hB
template<int SRC>
__global__ __launch_bounds__(256) void v10_gemm(const float* Xext, const float* W) {
    __shared__ float Ws[32][132];   // [kk][c], float4-stored, padded
    __shared__ float Xs[32][65];    // [kk][m], scalar-stored, stride 65 (conflict-free)

    const float* X = (SRC == 0) ? Xext
                   : (SRC == 1) ? (const float*)v9_hA : (const float*)v9_hB;

    const int tid = threadIdx.x;
    const int m0  = blockIdx.x * 64;
    const int ty  = tid >> 4;       // 0..15 row group
    const int tx  = tid & 15;       // 0..15 col group

    float acc[4][8];
#pragma unroll
    for (int r = 0; r < 4; r++)
#pragma unroll
        for (int c = 0; c < 8; c++) acc[r][c] = 0.f;

    for (int k0 = 0; k0 < 128; k0 += 32) {
        // load W chunk (32x128) via float4: 1024 float4 / 256 threads = 4 each
#pragma unroll
        for (int i = 0; i < 4; i++) {
            int idx = tid + i * 256;
            int kk  = idx >> 5;
            int c4  = idx & 31;
            float4 w = *(const float4*)&W[(k0 + kk) * 128 + c4 * 4];
            *(float4*)&Ws[kk][c4 * 4] = w;
        }
        // load X chunk as float4 rows, scatter transposed to Xs (scalar stores)
        // 64 rows x 8 float4 = 512 float4 / 256 threads = 2 each
#pragma unroll
        for (int i = 0; i < 2; i++) {
            int idx = tid + i * 256;          // 0..511
            int m   = idx >> 3;               // 0..63
            int q4  = idx & 7;                // float4 index within 32-k chunk
            int row = m0 + m;
            float4 v = make_float4(0.f, 0.f, 0.f, 0.f);
            if (row < N_NODES) v = *(const float4*)&X[row * 128 + k0 + q4 * 4];
            Xs[q4 * 4 + 0][m] = v.x;
            Xs[q4 * 4 + 1][m] = v.y;
            Xs[q4 * 4 + 2][m] = v.z;
            Xs[q4 * 4 + 3][m] = v.w;
        }
        __syncthreads();
#pragma unroll
        for (int kk = 0; kk < 32; kk++) {
            float a0 = Xs[kk][ty * 4 + 0];
            float a1 = Xs[kk][ty * 4 + 1];
            float a2 = Xs[kk][ty * 4 + 2];
            float a3 = Xs[kk][ty * 4 + 3];
            float4 b0 = *(const float4*)&Ws[kk][tx * 8];
            float4 b1 = *(const float4*)&Ws[kk][tx * 8 + 4];
            float a4[4] = {a0, a1, a2, a3};
            float b8[8] = {b0.x, b0.y, b0.z, b0.w, b1.x, b1.y, b1.z, b1.w};
#pragma unroll
            for (int r = 0; r < 4; r++)
#pragma unroll
                for (int c = 0; c < 8; c++)
                    acc[r][c] = fmaf(a4[r], b8[c], acc[r][c]);
        }
        __syncthreads();
    }
#pragma unroll
    for (int r = 0; r < 4; r++) {
        int row = m0 + ty * 4 + r;
        if (row < N_NODES) {
            float4 o0 = make_float4(acc[r][0], acc[r][1], acc[r][2], acc[r][3]);
            float4 o1 = make_float4(acc[r][4], acc[r][5], acc[r][6], acc[r][7]);
            *(float4*)&v9_T[row * 128 + tx * 8]     = o0;
            *(float4*)&v9_T[row * 128 + tx * 8 + 4] = o1;
        }
    }
}

// ---------------- aggregation: one warp per node, float4 gathers ----------------
// out[n] = relu?( dinv[n] * sum_s dinv[s]*v9_T[s] + b )
template<int DST, int RELU>
__global__ __launch_bounds__(256) void v10_agg(const float* bias) {
    int node = (blockIdx.x * blockDim.x + threadIdx.x) >> 5;
    int lane = threadIdx.x & 31;
    if (node >= N_NODES) return;

    int beg = v9_rowptr[node];
    int end = v9_rowptr[node + 1];

    float ax = 0.f, ay = 0.f, az = 0.f, aw = 0.f;
    int e = beg;
    for (; e + 1 < end; e += 2) {
        int2 e0 = v9_edge[e];
        int2 e1 = v9_edge[e + 1];
        float w0 = __int_as_float(e0.y);
        float w1 = __int_as_float(e1.y);
        float4 v0 = *(const float4*)&v9_T[e0.x * 128 + lane * 4];
        float4 v1 = *(const float4*)&v9_T[e1.x * 128 + lane * 4];
        ax = fmaf(w0, v0.x, ax); ay = fmaf(w0, v0.y, ay);
        az = fmaf(w0, v0.z, az); aw = fmaf(w0, v0.w, aw);
        ax = fmaf(w1, v1.x, ax); ay = fmaf(w1, v1.y, ay);
        az = fmaf(w1, v1.z, az); aw = fmaf(w1, v1.w, aw);
    }
    if (e < end) {
        int2 e0 = v9_edge[e];
        float w = __int_as_float(e0.y);
        float4 v = *(const float4*)&v9_T[e0.x * 128 + lane * 4];
        ax = fmaf(w, v.x, ax); ay = fmaf(w, v.y, ay);
        az = fmaf(w, v.z, az); aw = fmaf(w, v.w, aw);
    }
    float dn = v9_dinv[node];
    float4 b = *(const float4*)&bias[lane * 4];
    float4 o;
    o.x = fmaf(ax, dn, b.x);
    o.y = fmaf(ay, dn, b.y);
    o.z = fmaf(az, dn, b.z);
    o.w = fmaf(aw, dn, b.w);
    if (RELU) {
        o.x = fmaxf(o.x, 0.f); o.y = fmaxf(o.y, 0.f);
        o.z = fmaxf(o.z, 0.f); o.w = fmaxf(o.w, 0.f);
    }
    float* Out = (DST == 1) ? v9_hA : v9_hB;
    *(float4*)&Out[node * 128 + lane * 4] = o;
}

// ---------------- pooling (batch sorted; reads v9_hA) ----------------
#define POOL_CHUNK 256
__global__ void v9_pool(const int* batch32) {
    int f  = threadIdx.x;                      // 128 threads = feature
    int n0 = blockIdx.x * POOL_CHUNK;
    int n1 = n0 + POOL_CHUNK;
    if (n1 > N_NODES) n1 = N_NODES;
    if (n0 >= N_NODES) return;

    int cur = ld_idx(batch32, n0);
    float local = 0.f;
    for (int n = n0; n < n1; n++) {
        int g = ld_idx(batch32, n);
        if (g != cur) {
            atomicAdd(&v9_pooled[cur * DIM + f], local);
            local = 0.f;
            cur = g;
        }
        local += v9_hA[n * DIM + f];
    }
    atomicAdd(&v9_pooled[cur * DIM + f], local);
}

// ---------------- classifier MLP ----------------
__global__ void v9_mlp1(const float* C1, const float* bc1) {
    int idx = blockIdx.x * blockDim.x + threadIdx.x;
    if (idx >= NUM_GRAPHS * DIM) return;
    int g = idx >> 7, c = idx & 127;
    float invc = 1.f / fmaxf((float)v9_cnt[g], 1.f);
    float s = bc1[c];
#pragma unroll 8
    for (int k = 0; k < 128; k++)
        s = fmaf(v9_pooled[g * 128 + k] * invc, C1[k * 128 + c], s);
    v9_hid[idx] = fmaxf(s, 0.f);
}

__global__ void v9_mlp2(const float* C2, const float* bc2, float* out) {
    int idx = threadIdx.x;
    if (idx >= NUM_GRAPHS * NUM_CLASSES) return;
    int g = idx / NUM_CLASSES, c = idx % NUM_CLASSES;
    float s = bc2[c];
#pragma unroll 8
    for (int k = 0; k < 128; k++)
        s = fmaf(v9_hid[g * 128 + k], C2[k * NUM_CLASSES + c], s);
    out[idx] = s;
}

// ---------------- launch ----------------
extern "C" void kernel_launch(void* const* d_in, const int* in_sizes, int n_in,
                              void* d_out, int out_size) {
    const float* x       = (const float*)d_in[0];
    const int*   ei32    = (const int*)d_in[1];     // width detected at runtime
    const int*   batch32 = (const int*)d_in[2];
    const float* W1 = (const float*)d_in[3];  const float* b1 = (const float*)d_in[4];
    const float* W2 = (const float*)d_in[5];  const float* b2 = (const float*)d_in[6];
    const float* W3 = (const float*)d_in[7];  const float* b3 = (const float*)d_in[8];
    const float* C1 = (const float*)d_in[9];  const float* bc1 = (const float*)d_in[10];
    const float* C2 = (const float*)d_in[11]; const float* bc2 = (const float*)d_in[12];
    float* out = (float*)d_out;

    const int TPB = 256;
    const int SEG_BLOCKS = (NSEG * 32 + TPB - 1) / TPB;

    v9_detect <<<1, 32>>>(ei32);
    v9_init   <<<(N_NODES + TPB - 1) / TPB, TPB>>>();
    v9_count  <<<(N_EDGES + TPB - 1) / TPB, TPB>>>(ei32, batch32);
    v9_rsqrt  <<<(N_NODES + TPB - 1) / TPB, TPB>>>();
    v9_segsum_k <<<SEG_BLOCKS, TPB>>>();
    v9_segscan_k<<<1, 32>>>();
    v9_rowptr_k <<<SEG_BLOCKS, TPB>>>();
    v9_fill   <<<(TOT_ENTRIES + TPB - 1) / TPB, TPB>>>(ei32);

    const int GEMM_BLOCKS = (N_NODES + 63) / 64;
    const int AGG_BLOCKS  = (N_NODES * 32 + TPB - 1) / TPB;

    v10_gemm<0><<<GEMM_BLOCKS, TPB>>>(x, W1);
    v10_agg<1, 1><<<AGG_BLOCKS, TPB>>>(b1);
    v10_gemm<1><<<GEMM_BLOCKS, TPB>>>(x, W2);
    v10_agg<2, 1><<<AGG_BLOCKS, TPB>>>(b2);
    v10_gemm<2><<<GEMM_BLOCKS, TPB>>>(x, W3);
    v10_agg<1, 0><<<AGG_BLOCKS, TPB>>>(b3);

    v9_pool<<<(N_NODES + POOL_CHUNK - 1) / POOL_CHUNK, 128>>>(batch32);
    v9_mlp1<<<(NUM_GRAPHS * DIM + TPB - 1) / TPB, TPB>>>(C1, bc1);
    v9_mlp2<<<1, 256>>>(C2, bc2, out);
}

// round 12
// speedup vs baseline: 1.1940x; 1.1899x over previous
#include <cuda_runtime.h>
#include <cuda_bf16.h>

#define N_NODES   50000
#define N_EDGES   800000
#define DIM       128
#define NUM_GRAPHS 64
#define NUM_CLASSES 3
#define TOT_ENTRIES (N_EDGES + N_NODES)
#define NSEG ((N_NODES + 127) / 128)       // 391

// ---------------- scratch (device globals; sanctioned, no allocation) ----------------
__device__ int   v9_is64;                  // 1 if index inputs are int64, 0 if int32
__device__ int   v9_deg[N_NODES];
__device__ float v9_dinv[N_NODES];
__device__ int   v9_segsum[NSEG];
__device__ int   v9_segoff[NSEG];
__device__ int   v9_rowptr[N_NODES + 1];
__device__ int   v9_cursor[N_NODES];
__device__ __align__(8)  int2  v9_edge[TOT_ENTRIES];   // (src, dinv[src] bits)
__device__ __align__(16) float v9_T [N_NODES * DIM];
__device__ __align__(16) float v9_hA[N_NODES * DIM];
__device__ __align__(16) float v9_hB[N_NODES * DIM];
__device__ __align__(16) float v9_pooled[NUM_GRAPHS * DIM];   // pooled sums of z
__device__ __align__(16) float v9_pooled2[NUM_GRAPHS * DIM];  // mean(z)*W3 + b3
__device__ int   v9_cnt[NUM_GRAPHS];
__device__ __align__(16) float v9_hid[NUM_GRAPHS * DIM];

// dtype-adaptive index load: element i of a logical index array.
__device__ __forceinline__ int ld_idx(const int* p, int i) {
    return v9_is64 ? p[2 * i] : p[i];
}

__device__ __forceinline__ int v9_incl_scan(int v, int lane) {
#pragma unroll
    for (int o = 1; o < 32; o <<= 1) {
        int n = __shfl_up_sync(0xffffffffu, v, o);
        if (lane >= o) v += n;
    }
    return v;
}

// ---------------- dtype detection (single warp) ----------------
__global__ void v9_detect(const int* ei32) {
    int lane = threadIdx.x;
    int acc = 0;
    for (int i = lane; i < 4096; i += 32) acc |= ei32[2 * i + 1];
#pragma unroll
    for (int o = 16; o > 0; o >>= 1) acc |= __shfl_down_sync(0xffffffffu, acc, o);
    if (lane == 0) v9_is64 = (acc == 0) ? 1 : 0;
}

// ---------------- preprocessing ----------------
__global__ void v9_init() {
    int i = blockIdx.x * blockDim.x + threadIdx.x;
    if (i < N_NODES) v9_deg[i] = 1;               // self-loop pre-counted
    if (i < NUM_GRAPHS * DIM) v9_pooled[i] = 0.f;
    if (i < NUM_GRAPHS) v9_cnt[i] = 0;
}

__global__ void v9_count(const int* ei32, const int* batch32) {
    int i = blockIdx.x * blockDim.x + threadIdx.x;
    if (i < N_EDGES) {
        int dst = ld_idx(ei32, N_EDGES + i);
        atomicAdd(&v9_deg[dst], 1);
    }
    if (i < N_NODES) {
        int g = ld_idx(batch32, i);
        atomicAdd(&v9_cnt[g], 1);
    }
}

__global__ void v9_rsqrt() {
    int i = blockIdx.x * blockDim.x + threadIdx.x;
    if (i < N_NODES) v9_dinv[i] = rsqrtf((float)v9_deg[i]);
}

__global__ void v9_segsum_k() {
    int w    = (blockIdx.x * blockDim.x + threadIdx.x) >> 5;
    int lane = threadIdx.x & 31;
    if (w >= NSEG) return;
    int s = 0;
#pragma unroll
    for (int c = 0; c < 4; c++) {
        int i = w * 128 + c * 32 + lane;
        if (i < N_NODES) s += v9_deg[i];
    }
#pragma unroll
    for (int o = 16; o > 0; o >>= 1) s += __shfl_down_sync(0xffffffffu, s, o);
    if (lane == 0) v9_segsum[w] = s;
}

__global__ void v9_segscan_k() {
    int lane = threadIdx.x;
    int carry = 0;
    for (int base = 0; base < NSEG; base += 32) {
        int i = base + lane;
        int v = (i < NSEG) ? v9_segsum[i] : 0;
        int s = v9_incl_scan(v, lane);
        if (i < NSEG) v9_segoff[i] = carry + s - v;
        carry += __shfl_sync(0xffffffffu, s, 31);
    }
}

__global__ void v9_rowptr_k() {
    int w    = (blockIdx.x * blockDim.x + threadIdx.x) >> 5;
    int lane = threadIdx.x & 31;
    if (w >= NSEG) return;
    int carry = v9_segoff[w];
#pragma unroll
    for (int c = 0; c < 4; c++) {
        int i = w * 128 + c * 32 + lane;
        int v = (i < N_NODES) ? v9_deg[i] : 0;
        int s = v9_incl_scan(v, lane);
        if (i < N_NODES) {
            int ex = carry + s - v;
            v9_rowptr[i] = ex;
            v9_cursor[i] = ex;
        }
        carry += __shfl_sync(0xffffffffu, s, 31);
    }
    if (w == NSEG - 1 && lane == 0) v9_rowptr[N_NODES] = carry;
}

// scatter edges + self-loops; record (src, dinv[src]) per entry
__global__ void v9_fill(const int* ei32) {
    int i = blockIdx.x * blockDim.x + threadIdx.x;
    if (i < N_EDGES) {
        int src = ld_idx(ei32, i);
        int dst = ld_idx(ei32, N_EDGES + i);
        int pos = atomicAdd(&v9_cursor[dst], 1);
        v9_edge[pos] = make_int2(src, __float_as_int(v9_dinv[src]));
    } else if (i < TOT_ENTRIES) {
        int n = i - N_EDGES;
        int pos = atomicAdd(&v9_cursor[n], 1);
        v9_edge[pos] = make_int2(n, __float_as_int(v9_dinv[n]));
    }
}

// ---------------- GEMM: v9_T[N,128] = src[N,128] @ W[128,128] ----------------
// smem-tiled, float4. BM=64 rows/block, 256 threads, 4x8 outputs each.
// SRC: 0 -> Xext, 1 -> v9_hA
template<int SRC>
__global__ __launch_bounds__(256) void v10_gemm(const float* Xext, const float* W) {
    __shared__ float Ws[32][132];
    __shared__ float Xs[32][65];

    const float* X = (SRC == 0) ? Xext : (const float*)v9_hA;

    const int tid = threadIdx.x;
    const int m0  = blockIdx.x * 64;
    const int ty  = tid >> 4;
    const int tx  = tid & 15;

    float acc[4][8];
#pragma unroll
    for (int r = 0; r < 4; r++)
#pragma unroll
        for (int c = 0; c < 8; c++) acc[r][c] = 0.f;

    for (int k0 = 0; k0 < 128; k0 += 32) {
#pragma unroll
        for (int i = 0; i < 4; i++) {
            int idx = tid + i * 256;
            int kk  = idx >> 5;
            int c4  = idx & 31;
            float4 w = *(const float4*)&W[(k0 + kk) * 128 + c4 * 4];
            *(float4*)&Ws[kk][c4 * 4] = w;
        }
#pragma unroll
        for (int i = 0; i < 2; i++) {
            int idx = tid + i * 256;
            int m   = idx >> 3;
            int q4  = idx & 7;
            int row = m0 + m;
            float4 v = make_float4(0.f, 0.f, 0.f, 0.f);
            if (row < N_NODES) v = *(const float4*)&X[row * 128 + k0 + q4 * 4];
            Xs[q4 * 4 + 0][m] = v.x;
            Xs[q4 * 4 + 1][m] = v.y;
            Xs[q4 * 4 + 2][m] = v.z;
            Xs[q4 * 4 + 3][m] = v.w;
        }
        __syncthreads();
#pragma unroll
        for (int kk = 0; kk < 32; kk++) {
            float a4[4];
            a4[0] = Xs[kk][ty * 4 + 0];
            a4[1] = Xs[kk][ty * 4 + 1];
            a4[2] = Xs[kk][ty * 4 + 2];
            a4[3] = Xs[kk][ty * 4 + 3];
            float4 b0 = *(const float4*)&Ws[kk][tx * 8];
            float4 b1 = *(const float4*)&Ws[kk][tx * 8 + 4];
            float b8[8] = {b0.x, b0.y, b0.z, b0.w, b1.x, b1.y, b1.z, b1.w};
#pragma unroll
            for (int r = 0; r < 4; r++)
#pragma unroll
                for (int c = 0; c < 8; c++)
                    acc[r][c] = fmaf(a4[r], b8[c], acc[r][c]);
        }
        __syncthreads();
    }
#pragma unroll
    for (int r = 0; r < 4; r++) {
        int row = m0 + ty * 4 + r;
        if (row < N_NODES) {
            float4 o0 = make_float4(acc[r][0], acc[r][1], acc[r][2], acc[r][3]);
            float4 o1 = make_float4(acc[r][4], acc[r][5], acc[r][6], acc[r][7]);
            *(float4*)&v9_T[row * 128 + tx * 8]     = o0;
            *(float4*)&v9_T[row * 128 + tx * 8 + 4] = o1;
        }
    }
}

// ---------------- aggregation: one warp per node, float4 gathers ----------------
// out[n] = relu?( dinv[n] * sum_s dinv[s]*In[s] + (BIAS? b : 0) )
// SRCBUF: 0 -> v9_T, 2 -> v9_hB.  DST: 1 -> v9_hA, 2 -> v9_hB
template<int SRCBUF, int DST, int RELU, int BIAS>
__global__ __launch_bounds__(256) void v12_agg(const float* bias) {
    int node = (blockIdx.x * blockDim.x + threadIdx.x) >> 5;
    int lane = threadIdx.x & 31;
    if (node >= N_NODES) return;

    const float* In = (SRCBUF == 0) ? v9_T : v9_hB;

    int beg = v9_rowptr[node];
    int end = v9_rowptr[node + 1];

    float ax = 0.f, ay = 0.f, az = 0.f, aw = 0.f;
    int e = beg;
    for (; e + 1 < end; e += 2) {
        int2 e0 = v9_edge[e];
        int2 e1 = v9_edge[e + 1];
        float w0 = __int_as_float(e0.y);
        float w1 = __int_as_float(e1.y);
        float4 v0 = *(const float4*)&In[e0.x * 128 + lane * 4];
        float4 v1 = *(const float4*)&In[e1.x * 128 + lane * 4];
        ax = fmaf(w0, v0.x, ax); ay = fmaf(w0, v0.y, ay);
        az = fmaf(w0, v0.z, az); aw = fmaf(w0, v0.w, aw);
        ax = fmaf(w1, v1.x, ax); ay = fmaf(w1, v1.y, ay);
        az = fmaf(w1, v1.z, az); aw = fmaf(w1, v1.w, aw);
    }
    if (e < end) {
        int2 e0 = v9_edge[e];
        float w = __int_as_float(e0.y);
        float4 v = *(const float4*)&In[e0.x * 128 + lane * 4];
        ax = fmaf(w, v.x, ax); ay = fmaf(w, v.y, ay);
        az = fmaf(w, v.z, az); aw = fmaf(w, v.w, aw);
    }
    float dn = v9_dinv[node];
    float4 o;
    if (BIAS) {
        float4 b = *(const float4*)&bias[lane * 4];
        o.x = fmaf(ax, dn, b.x);
        o.y = fmaf(ay, dn, b.y);
        o.z = fmaf(az, dn, b.z);
        o.w = fmaf(aw, dn, b.w);
    } else {
        o.x = ax * dn; o.y = ay * dn; o.z = az * dn; o.w = aw * dn;
    }
    if (RELU) {
        o.x = fmaxf(o.x, 0.f); o.y = fmaxf(o.y, 0.f);
        o.z = fmaxf(o.z, 0.f); o.w = fmaxf(o.w, 0.f);
    }
    float* Out = (DST == 1) ? v9_hA : v9_hB;
    *(float4*)&Out[node * 128 + lane * 4] = o;
}

// ---------------- pooling (batch sorted; reads v9_hA) ----------------
#define POOL_CHUNK 256
__global__ void v9_pool(const int* batch32) {
    int f  = threadIdx.x;
    int n0 = blockIdx.x * POOL_CHUNK;
    int n1 = n0 + POOL_CHUNK;
    if (n1 > N_NODES) n1 = N_NODES;
    if (n0 >= N_NODES) return;

    int cur = ld_idx(batch32, n0);
    float local = 0.f;
    for (int n = n0; n < n1; n++) {
        int g = ld_idx(batch32, n);
        if (g != cur) {
            atomicAdd(&v9_pooled[cur * DIM + f], local);
            local = 0.f;
            cur = g;
        }
        local += v9_hA[n * DIM + f];
    }
    atomicAdd(&v9_pooled[cur * DIM + f], local);
}

// ---------------- folded W3: pooled2 = mean(z) @ W3 + b3  (64x128x128) ----------------
__global__ void v12_wfold(const float* W3, const float* b3) {
    __shared__ float Ps[128];
    int g = blockIdx.x, c = threadIdx.x;
    float invc = 1.f / fmaxf((float)v9_cnt[g], 1.f);
    Ps[c] = v9_pooled[g * 128 + c] * invc;
    __syncthreads();
    float s = b3[c];
#pragma unroll 8
    for (int k = 0; k < 128; k++)
        s = fmaf(Ps[k], W3[k * 128 + c], s);
    v9_pooled2[g * 128 + c] = s;
}

// ---------------- classifier MLP ----------------
__global__ void v12_mlp1(const float* C1, const float* bc1) {
    int idx = blockIdx.x * blockDim.x + threadIdx.x;
    if (idx >= NUM_GRAPHS * DIM) return;
    int g = idx >> 7, c = idx & 127;
    float s = bc1[c];
#pragma unroll 8
    for (int k = 0; k < 128; k++)
        s = fmaf(v9_pooled2[g * 128 + k], C1[k * 128 + c], s);
    v9_hid[idx] = fmaxf(s, 0.f);
}

__global__ void v9_mlp2(const float* C2, const float* bc2, float* out) {
    int idx = threadIdx.x;
    if (idx >= NUM_GRAPHS * NUM_CLASSES) return;
    int g = idx / NUM_CLASSES, c = idx % NUM_CLASSES;
    float s = bc2[c];
#pragma unroll 8
    for (int k = 0; k < 128; k++)
        s = fmaf(v9_hid[g * 128 + k], C2[k * NUM_CLASSES + c], s);
    out[idx] = s;
}

// ---------------- launch ----------------
extern "C" void kernel_launch(void* const* d_in, const int* in_sizes, int n_in,
                              void* d_out, int out_size) {
    const float* x       = (const float*)d_in[0];
    const int*   ei32    = (const int*)d_in[1];     // width detected at runtime
    const int*   batch32 = (const int*)d_in[2];
    const float* W1 = (const float*)d_in[3];  const float* b1 = (const float*)d_in[4];
    const float* W2 = (const float*)d_in[5];  const float* b2 = (const float*)d_in[6];
    const float* W3 = (const float*)d_in[7];  const float* b3 = (const float*)d_in[8];
    const float* C1 = (const float*)d_in[9];  const float* bc1 = (const float*)d_in[10];
    const float* C2 = (const float*)d_in[11]; const float* bc2 = (const float*)d_in[12];
    float* out = (float*)d_out;

    const int TPB = 256;
    const int SEG_BLOCKS  = (NSEG * 32 + TPB - 1) / TPB;
    const int GEMM_BLOCKS = (N_NODES + 63) / 64;
    const int AGG_BLOCKS  = (N_NODES * 32 + TPB - 1) / TPB;

    // fork preprocessing onto a side stream, overlapped with gemm1 (x@W1 needs no graph data)
    cudaStream_t s2;
    cudaStreamCreateWithFlags(&s2, cudaStreamNonBlocking);
    cudaEvent_t evF, evJ;
    cudaEventCreateWithFlags(&evF, cudaEventDisableTiming);
    cudaEventCreateWithFlags(&evJ, cudaEventDisableTiming);

    cudaEventRecord(evF, 0);
    cudaStreamWaitEvent(s2, evF, 0);

    v9_detect   <<<1, 32, 0, s2>>>(ei32);
    v9_init     <<<(N_NODES + TPB - 1) / TPB, TPB, 0, s2>>>();
    v9_count    <<<(N_EDGES + TPB - 1) / TPB, TPB, 0, s2>>>(ei32, batch32);
    v9_rsqrt    <<<(N_NODES + TPB - 1) / TPB, TPB, 0, s2>>>();
    v9_segsum_k <<<SEG_BLOCKS, TPB, 0, s2>>>();
    v9_segscan_k<<<1, 32, 0, s2>>>();
    v9_rowptr_k <<<SEG_BLOCKS, TPB, 0, s2>>>();
    v9_fill     <<<(TOT_ENTRIES + TPB - 1) / TPB, TPB, 0, s2>>>(ei32);
    cudaEventRecord(evJ, s2);

    // layer-1 GEMM overlaps the preprocessing
    v10_gemm<0><<<GEMM_BLOCKS, TPB>>>(x, W1);

    cudaStreamWaitEvent(0, evJ, 0);

    // layer 1: aggregate T -> hA (relu, +b1)
    v12_agg<0, 1, 1, 1><<<AGG_BLOCKS, TPB>>>(b1);
    // layer 2: hA @ W2 -> T ; aggregate -> hB (relu, +b2)
    v10_gemm<1><<<GEMM_BLOCKS, TPB>>>(x, W2);
    v12_agg<0, 2, 1, 1><<<AGG_BLOCKS, TPB>>>(b2);
    // layer 3 folded: z = A_norm * hB -> hA (no bias/relu); pool; then (mean z)@W3+b3
    v12_agg<2, 1, 0, 0><<<AGG_BLOCKS, TPB>>>(b3);
    v9_pool<<<(N_NODES + POOL_CHUNK - 1) / POOL_CHUNK, 128>>>(batch32);
    v12_wfold<<<NUM_GRAPHS, 128>>>(W3, b3);

    // classifier
    v12_mlp1<<<(NUM_GRAPHS * DIM + TPB - 1) / TPB, TPB>>>(C1, bc1);
    v9_mlp2<<<1, 256>>>(C2, bc2, out);
}

// round 13
// speedup vs baseline: 1.4369x; 1.2034x over previous
#include <cuda_runtime.h>
#include <cuda_bf16.h>
#include <cstring>

#define N_NODES   50000
#define N_EDGES   800000
#define DIM       128
#define NUM_GRAPHS 64
#define NUM_CLASSES 3
#define TOT_ENTRIES (N_EDGES + N_NODES)
#define NSEG ((N_NODES + 127) / 128)       // 391

// ---------------- scratch (device globals; sanctioned, no allocation) ----------------
__device__ int   v9_is64;                  // 1 if index inputs are int64, 0 if int32
__device__ int   v9_deg[N_NODES];
__device__ float v9_dinv[N_NODES];
__device__ int   v9_segsum[NSEG];
__device__ int   v9_segoff[NSEG];
__device__ int   v9_rowptr[N_NODES + 1];
__device__ int   v9_cursor[N_NODES];
__device__ __align__(8)  int2  v9_edge[TOT_ENTRIES];   // (src, dinv[src] bits)
__device__ __align__(16) float v9_T [N_NODES * DIM];
__device__ __align__(16) float v9_hA[N_NODES * DIM];
__device__ __align__(16) float v9_hB[N_NODES * DIM];
__device__ __align__(16) float v9_pooled[NUM_GRAPHS * DIM];   // pooled sums of z
__device__ __align__(16) float v9_pooled2[NUM_GRAPHS * DIM];  // mean(z)*W3 + b3
__device__ int   v9_cnt[NUM_GRAPHS];
__device__ __align__(16) float v9_hid[NUM_GRAPHS * DIM];

// dtype-adaptive index load
__device__ __forceinline__ int ld_idx(const int* p, int i) {
    return v9_is64 ? p[2 * i] : p[i];
}

__device__ __forceinline__ int v9_incl_scan(int v, int lane) {
#pragma unroll
    for (int o = 1; o < 32; o <<= 1) {
        int n = __shfl_up_sync(0xffffffffu, v, o);
        if (lane >= o) v += n;
    }
    return v;
}

// pack two floats as bf16x2 (x -> low half, y -> high half)
__device__ __forceinline__ unsigned pk_bf2(float x, float y) {
    __nv_bfloat162 h = __floats2bfloat162_rn(x, y);
    unsigned u; memcpy(&u, &h, 4); return u;
}
__device__ __forceinline__ float bf_hi(float x) {
    return __bfloat162float(__float2bfloat16_rn(x));
}

__device__ __forceinline__ void mma_bf16(float* d, const unsigned* a,
                                         unsigned b0, unsigned b1) {
    asm volatile(
        "mma.sync.aligned.m16n8k16.row.col.f32.bf16.bf16.f32 "
        "{%0,%1,%2,%3}, {%4,%5,%6,%7}, {%8,%9}, {%0,%1,%2,%3};\n"
        : "+f"(d[0]), "+f"(d[1]), "+f"(d[2]), "+f"(d[3])
        : "r"(a[0]), "r"(a[1]), "r"(a[2]), "r"(a[3]), "r"(b0), "r"(b1));
}

// ---------------- dtype detection (single warp) ----------------
__global__ void v9_detect(const int* ei32) {
    int lane = threadIdx.x;
    int acc = 0;
    for (int i = lane; i < 4096; i += 32) acc |= ei32[2 * i + 1];
#pragma unroll
    for (int o = 16; o > 0; o >>= 1) acc |= __shfl_down_sync(0xffffffffu, acc, o);
    if (lane == 0) v9_is64 = (acc == 0) ? 1 : 0;
}

// ---------------- preprocessing ----------------
__global__ void v9_init() {
    int i = blockIdx.x * blockDim.x + threadIdx.x;
    if (i < N_NODES) v9_deg[i] = 1;               // self-loop pre-counted
    if (i < NUM_GRAPHS * DIM) v9_pooled[i] = 0.f;
    if (i < NUM_GRAPHS) v9_cnt[i] = 0;
}

__global__ void v9_count(const int* ei32, const int* batch32) {
    int i = blockIdx.x * blockDim.x + threadIdx.x;
    if (i < N_EDGES) {
        int dst = ld_idx(ei32, N_EDGES + i);
        atomicAdd(&v9_deg[dst], 1);
    }
    if (i < N_NODES) {
        int g = ld_idx(batch32, i);
        atomicAdd(&v9_cnt[g], 1);
    }
}

__global__ void v9_rsqrt() {
    int i = blockIdx.x * blockDim.x + threadIdx.x;
    if (i < N_NODES) v9_dinv[i] = rsqrtf((float)v9_deg[i]);
}

__global__ void v9_segsum_k() {
    int w    = (blockIdx.x * blockDim.x + threadIdx.x) >> 5;
    int lane = threadIdx.x & 31;
    if (w >= NSEG) return;
    int s = 0;
#pragma unroll
    for (int c = 0; c < 4; c++) {
        int i = w * 128 + c * 32 + lane;
        if (i < N_NODES) s += v9_deg[i];
    }
#pragma unroll
    for (int o = 16; o > 0; o >>= 1) s += __shfl_down_sync(0xffffffffu, s, o);
    if (lane == 0) v9_segsum[w] = s;
}

__global__ void v9_segscan_k() {
    int lane = threadIdx.x;
    int carry = 0;
    for (int base = 0; base < NSEG; base += 32) {
        int i = base + lane;
        int v = (i < NSEG) ? v9_segsum[i] : 0;
        int s = v9_incl_scan(v, lane);
        if (i < NSEG) v9_segoff[i] = carry + s - v;
        carry += __shfl_sync(0xffffffffu, s, 31);
    }
}

__global__ void v9_rowptr_k() {
    int w    = (blockIdx.x * blockDim.x + threadIdx.x) >> 5;
    int lane = threadIdx.x & 31;
    if (w >= NSEG) return;
    int carry = v9_segoff[w];
#pragma unroll
    for (int c = 0; c < 4; c++) {
        int i = w * 128 + c * 32 + lane;
        int v = (i < N_NODES) ? v9_deg[i] : 0;
        int s = v9_incl_scan(v, lane);
        if (i < N_NODES) {
            int ex = carry + s - v;
            v9_rowptr[i] = ex;
            v9_cursor[i] = ex;
        }
        carry += __shfl_sync(0xffffffffu, s, 31);
    }
    if (w == NSEG - 1 && lane == 0) v9_rowptr[N_NODES] = carry;
}

__global__ void v9_fill(const int* ei32) {
    int i = blockIdx.x * blockDim.x + threadIdx.x;
    if (i < N_EDGES) {
        int src = ld_idx(ei32, i);
        int dst = ld_idx(ei32, N_EDGES + i);
        int pos = atomicAdd(&v9_cursor[dst], 1);
        v9_edge[pos] = make_int2(src, __float_as_int(v9_dinv[src]));
    } else if (i < TOT_ENTRIES) {
        int n = i - N_EDGES;
        int pos = atomicAdd(&v9_cursor[n], 1);
        v9_edge[pos] = make_int2(n, __float_as_int(v9_dinv[n]));
    }
}

// ---------------- tensor-core GEMM (split-bf16): v9_T = src @ W ----------------
// Block: 128 rows, 8 warps x 16 rows x 128 cols. mma.m16n8k16, 3-way bf16 split.
// SRC: 0 -> Xext, 1 -> v9_hA
template<int SRC>
__global__ __launch_bounds__(256) void v13_gemm(const float* Xext, const float* W) {
    __shared__ unsigned Bs_hi[128][9];   // [n][k2], k2: (k-k0)/2, padded stride 9
    __shared__ unsigned Bs_lo[128][9];

    const float* X = (SRC == 0) ? Xext : (const float*)v9_hA;

    const int tid  = threadIdx.x;
    const int warp = tid >> 5;
    const int lane = tid & 31;
    const int gid  = lane >> 2;          // 0..7
    const int tig  = lane & 3;           // 0..3
    const int mw   = blockIdx.x * 128 + warp * 16;   // warp row base

    float acc[16][4];
#pragma unroll
    for (int nt = 0; nt < 16; nt++)
#pragma unroll
        for (int j = 0; j < 4; j++) acc[nt][j] = 0.f;

    const int r0 = mw + gid;             // fragment row A (low)
    const int r1 = mw + gid + 8;         // fragment row B (high)
    const bool v0 = (r0 < N_NODES);
    const bool v1 = (r1 < N_NODES);

    for (int kc = 0; kc < 8; kc++) {
        const int k0 = kc * 16;
        // stage W chunk [k0..k0+15][0..127] as bf16 hi/lo pairs along k
        // 1024 (k2,n) pairs, 4 per thread
#pragma unroll
        for (int i = 0; i < 4; i++) {
            int p  = tid + i * 256;      // 0..1023
            int n  = p & 127;
            int k2 = p >> 7;             // 0..7
            float w0 = W[(k0 + 2 * k2) * 128 + n];
            float w1 = W[(k0 + 2 * k2 + 1) * 128 + n];
            float h0 = bf_hi(w0), h1 = bf_hi(w1);
            Bs_hi[n][k2] = pk_bf2(h0, h1);
            Bs_lo[n][k2] = pk_bf2(w0 - h0, w1 - h1);
        }
        __syncthreads();

        // A fragments: rows r0/r1, k = k0 + tig*2 + {0,1} and +8
        float2 x00 = make_float2(0.f, 0.f), x01 = x00, x10 = x00, x11 = x00;
        if (v0) {
            x00 = *(const float2*)&X[r0 * 128 + k0 + tig * 2];
            x01 = *(const float2*)&X[r0 * 128 + k0 + tig * 2 + 8];
        }
        if (v1) {
            x10 = *(const float2*)&X[r1 * 128 + k0 + tig * 2];
            x11 = *(const float2*)&X[r1 * 128 + k0 + tig * 2 + 8];
        }
        float h;
        unsigned a_hi[4], a_lo[4];
        {
            float hx, hy;
            hx = bf_hi(x00.x); hy = bf_hi(x00.y);
            a_hi[0] = pk_bf2(hx, hy); a_lo[0] = pk_bf2(x00.x - hx, x00.y - hy);
            hx = bf_hi(x10.x); hy = bf_hi(x10.y);
            a_hi[1] = pk_bf2(hx, hy); a_lo[1] = pk_bf2(x10.x - hx, x10.y - hy);
            hx = bf_hi(x01.x); hy = bf_hi(x01.y);
            a_hi[2] = pk_bf2(hx, hy); a_lo[2] = pk_bf2(x01.x - hx, x01.y - hy);
            hx = bf_hi(x11.x); hy = bf_hi(x11.y);
            a_hi[3] = pk_bf2(hx, hy); a_lo[3] = pk_bf2(x11.x - hx, x11.y - hy);
        }
        (void)h;

#pragma unroll
        for (int nt = 0; nt < 16; nt++) {
            int n = nt * 8 + gid;
            unsigned bh0 = Bs_hi[n][tig];
            unsigned bh1 = Bs_hi[n][tig + 4];
            unsigned bl0 = Bs_lo[n][tig];
            unsigned bl1 = Bs_lo[n][tig + 4];
            mma_bf16(acc[nt], a_hi, bh0, bh1);   // hi*hi
            mma_bf16(acc[nt], a_hi, bl0, bl1);   // hi*lo
            mma_bf16(acc[nt], a_lo, bh0, bh1);   // lo*hi
        }
        __syncthreads();
    }

    // epilogue: D fragment -> v9_T
#pragma unroll
    for (int nt = 0; nt < 16; nt++) {
        int n = nt * 8 + tig * 2;
        if (v0) *(float2*)&v9_T[r0 * 128 + n] = make_float2(acc[nt][0], acc[nt][1]);
        if (v1) *(float2*)&v9_T[r1 * 128 + n] = make_float2(acc[nt][2], acc[nt][3]);
    }
}

// ---------------- aggregation: one warp per node, float4 gathers ----------------
// SRCBUF: 0 -> v9_T, 2 -> v9_hB.  DST: 1 -> v9_hA, 2 -> v9_hB
template<int SRCBUF, int DST, int RELU, int BIAS>
__global__ __launch_bounds__(256) void v12_agg(const float* bias) {
    int node = (blockIdx.x * blockDim.x + threadIdx.x) >> 5;
    int lane = threadIdx.x & 31;
    if (node >= N_NODES) return;

    const float* In = (SRCBUF == 0) ? v9_T : v9_hB;

    int beg = v9_rowptr[node];
    int end = v9_rowptr[node + 1];

    float ax = 0.f, ay = 0.f, az = 0.f, aw = 0.f;
    int e = beg;
    for (; e + 1 < end; e += 2) {
        int2 e0 = v9_edge[e];
        int2 e1 = v9_edge[e + 1];
        float w0 = __int_as_float(e0.y);
        float w1 = __int_as_float(e1.y);
        float4 q0 = *(const float4*)&In[e0.x * 128 + lane * 4];
        float4 q1 = *(const float4*)&In[e1.x * 128 + lane * 4];
        ax = fmaf(w0, q0.x, ax); ay = fmaf(w0, q0.y, ay);
        az = fmaf(w0, q0.z, az); aw = fmaf(w0, q0.w, aw);
        ax = fmaf(w1, q1.x, ax); ay = fmaf(w1, q1.y, ay);
        az = fmaf(w1, q1.z, az); aw = fmaf(w1, q1.w, aw);
    }
    if (e < end) {
        int2 e0 = v9_edge[e];
        float w = __int_as_float(e0.y);
        float4 q = *(const float4*)&In[e0.x * 128 + lane * 4];
        ax = fmaf(w, q.x, ax); ay = fmaf(w, q.y, ay);
        az = fmaf(w, q.z, az); aw = fmaf(w, q.w, aw);
    }
    float dn = v9_dinv[node];
    float4 o;
    if (BIAS) {
        float4 b = *(const float4*)&bias[lane * 4];
        o.x = fmaf(ax, dn, b.x);
        o.y = fmaf(ay, dn, b.y);
        o.z = fmaf(az, dn, b.z);
        o.w = fmaf(aw, dn, b.w);
    } else {
        o.x = ax * dn; o.y = ay * dn; o.z = az * dn; o.w = aw * dn;
    }
    if (RELU) {
        o.x = fmaxf(o.x, 0.f); o.y = fmaxf(o.y, 0.f);
        o.z = fmaxf(o.z, 0.f); o.w = fmaxf(o.w, 0.f);
    }
    float* Out = (DST == 1) ? v9_hA : v9_hB;
    *(float4*)&Out[node * 128 + lane * 4] = o;
}

// ---------------- pooling (batch sorted; reads v9_hA) ----------------
#define POOL_CHUNK 256
__global__ void v9_pool(const int* batch32) {
    int f  = threadIdx.x;
    int n0 = blockIdx.x * POOL_CHUNK;
    int n1 = n0 + POOL_CHUNK;
    if (n1 > N_NODES) n1 = N_NODES;
    if (n0 >= N_NODES) return;

    int cur = ld_idx(batch32, n0);
    float local = 0.f;
    for (int n = n0; n < n1; n++) {
        int g = ld_idx(batch32, n);
        if (g != cur) {
            atomicAdd(&v9_pooled[cur * DIM + f], local);
            local = 0.f;
            cur = g;
        }
        local += v9_hA[n * DIM + f];
    }
    atomicAdd(&v9_pooled[cur * DIM + f], local);
}

// ---------------- folded W3: pooled2 = mean(z) @ W3 + b3 ----------------
__global__ void v12_wfold(const float* W3, const float* b3) {
    __shared__ float Ps[128];
    int g = blockIdx.x, c = threadIdx.x;
    float invc = 1.f / fmaxf((float)v9_cnt[g], 1.f);
    Ps[c] = v9_pooled[g * 128 + c] * invc;
    __syncthreads();
    float s = b3[c];
#pragma unroll 8
    for (int k = 0; k < 128; k++)
        s = fmaf(Ps[k], W3[k * 128 + c], s);
    v9_pooled2[g * 128 + c] = s;
}

// ---------------- classifier MLP ----------------
__global__ void v12_mlp1(const float* C1, const float* bc1) {
    int idx = blockIdx.x * blockDim.x + threadIdx.x;
    if (idx >= NUM_GRAPHS * DIM) return;
    int g = idx >> 7, c = idx & 127;
    float s = bc1[c];
#pragma unroll 8
    for (int k = 0; k < 128; k++)
        s = fmaf(v9_pooled2[g * 128 + k], C1[k * 128 + c], s);
    v9_hid[idx] = fmaxf(s, 0.f);
}

__global__ void v9_mlp2(const float* C2, const float* bc2, float* out) {
    int idx = threadIdx.x;
    if (idx >= NUM_GRAPHS * NUM_CLASSES) return;
    int g = idx / NUM_CLASSES, c = idx % NUM_CLASSES;
    float s = bc2[c];
#pragma unroll 8
    for (int k = 0; k < 128; k++)
        s = fmaf(v9_hid[g * 128 + k], C2[k * NUM_CLASSES + c], s);
    out[idx] = s;
}

// ---------------- launch ----------------
extern "C" void kernel_launch(void* const* d_in, const int* in_sizes, int n_in,
                              void* d_out, int out_size) {
    const float* x       = (const float*)d_in[0];
    const int*   ei32    = (const int*)d_in[1];
    const int*   batch32 = (const int*)d_in[2];
    const float* W1 = (const float*)d_in[3];  const float* b1 = (const float*)d_in[4];
    const float* W2 = (const float*)d_in[5];  const float* b2 = (const float*)d_in[6];
    const float* W3 = (const float*)d_in[7];  const float* b3 = (const float*)d_in[8];
    const float* C1 = (const float*)d_in[9];  const float* bc1 = (const float*)d_in[10];
    const float* C2 = (const float*)d_in[11]; const float* bc2 = (const float*)d_in[12];
    float* out = (float*)d_out;

    const int TPB = 256;
    const int SEG_BLOCKS  = (NSEG * 32 + TPB - 1) / TPB;
    const int GEMM_BLOCKS = (N_NODES + 127) / 128;
    const int AGG_BLOCKS  = (N_NODES * 32 + TPB - 1) / TPB;

    // fork preprocessing onto a side stream, overlapped with gemm1
    cudaStream_t s2;
    cudaStreamCreateWithFlags(&s2, cudaStreamNonBlocking);
    cudaEvent_t evF, evJ;
    cudaEventCreateWithFlags(&evF, cudaEventDisableTiming);
    cudaEventCreateWithFlags(&evJ, cudaEventDisableTiming);

    cudaEventRecord(evF, 0);
    cudaStreamWaitEvent(s2, evF, 0);

    v9_detect   <<<1, 32, 0, s2>>>(ei32);
    v9_init     <<<(N_NODES + TPB - 1) / TPB, TPB, 0, s2>>>();
    v9_count    <<<(N_EDGES + TPB - 1) / TPB, TPB, 0, s2>>>(ei32, batch32);
    v9_rsqrt    <<<(N_NODES + TPB - 1) / TPB, TPB, 0, s2>>>();
    v9_segsum_k <<<SEG_BLOCKS, TPB, 0, s2>>>();
    v9_segscan_k<<<1, 32, 0, s2>>>();
    v9_rowptr_k <<<SEG_BLOCKS, TPB, 0, s2>>>();
    v9_fill     <<<(TOT_ENTRIES + TPB - 1) / TPB, TPB, 0, s2>>>(ei32);
    cudaEventRecord(evJ, s2);

    // layer-1 GEMM overlaps the preprocessing
    v13_gemm<0><<<GEMM_BLOCKS, TPB>>>(x, W1);

    cudaStreamWaitEvent(0, evJ, 0);

    // layer 1: aggregate T -> hA (relu, +b1)
    v12_agg<0, 1, 1, 1><<<AGG_BLOCKS, TPB>>>(b1);
    // layer 2: hA @ W2 -> T ; aggregate -> hB (relu, +b2)
    v13_gemm<1><<<GEMM_BLOCKS, TPB>>>(x, W2);
    v12_agg<0, 2, 1, 1><<<AGG_BLOCKS, TPB>>>(b2);
    // layer 3 folded: z = A_norm * hB -> hA; pool; then (mean z)@W3+b3
    v12_agg<2, 1, 0, 0><<<AGG_BLOCKS, TPB>>>(b3);
    v9_pool<<<(N_NODES + POOL_CHUNK - 1) / POOL_CHUNK, 128>>>(batch32);
    v12_wfold<<<NUM_GRAPHS, 128>>>(W3, b3);

    // classifier
    v12_mlp1<<<(NUM_GRAPHS * DIM + TPB - 1) / TPB, TPB>>>(C1, bc1);
    v9_mlp2<<<1, 256>>>(C2, bc2, out);
}